// round 9
// baseline (speedup 1.0000x reference)
#include <cuda_runtime.h>
#include <cstddef>

// Problem constants (match reference)
#define BATCH 256
#define SEQ   780
#define DIM   1024
#define MAXT  195
#define THREADS 128   // 128 lanes x 32B = one 4KB row per CTA

// 256-bit global load, L1-bypass / non-coherent (sm_100+: LDG.E.256)
__device__ __forceinline__ void ldg256_nc(const float* p, float* r) {
    asm volatile(
        "ld.global.nc.v8.f32 {%0,%1,%2,%3,%4,%5,%6,%7}, [%8];"
        : "=f"(r[0]), "=f"(r[1]), "=f"(r[2]), "=f"(r[3]),
          "=f"(r[4]), "=f"(r[5]), "=f"(r[6]), "=f"(r[7])
        : "l"(p));
}

// 256-bit global store, streaming / evict-first (write-once data):
// lets L2 flush fully-dirty spans eagerly -> better DRAM writeback batching.
__device__ __forceinline__ void stg256_cs(float* p, const float* r) {
    asm volatile(
        "st.global.cs.v8.f32 [%0], {%1,%2,%3,%4,%5,%6,%7,%8};"
        :: "l"(p),
           "f"(r[0]), "f"(r[1]), "f"(r[2]), "f"(r[3]),
           "f"(r[4]), "f"(r[5]), "f"(r[6]), "f"(r[7])
        : "memory");
}

// One CTA per (batch, pooled-token) — the proven best shape.
// Valid: 4 independent 256-bit gathers -> average -> one streaming 256-bit store.
// Invalid: one streaming 256-bit zero store (output poisoned; must write).
__global__ void __launch_bounds__(THREADS, 12)
avg_pool_merge_v8s_kernel(const float* __restrict__ hs,
                          const int*   __restrict__ grid_thw,
                          float*       __restrict__ out,
                          float*       __restrict__ out_att)
{
    const int j = blockIdx.x;          // pooled token index [0, MAXT)
    const int b = blockIdx.y;          // batch index
    const int t = threadIdx.x;         // 8-float lane [0, 128)

    const int W2 = grid_thw[b * 3 + 2] >> 1;
    const int Hp = grid_thw[b * 3 + 1] >> 2;
    const int Wp = W2 >> 1;
    const int n_out = Hp * Wp;

    float* o = out + ((size_t)b * MAXT + j) * DIM + t * 8;

    if (j >= n_out) {
        float z[8] = {0.f, 0.f, 0.f, 0.f, 0.f, 0.f, 0.f, 0.f};
        stg256_cs(o, z);
        if (t == 0 && out_att) out_att[(size_t)b * MAXT + j] = 0.f;
        return;
    }

    const int r = j / Wp;
    const int c = j - r * Wp;
    const int base = (2 * r) * W2 + 2 * c;  // top-left of the 2x2 window

    const float* srow = hs + (size_t)b * SEQ * DIM
                           + (size_t)base * DIM + t * 8;

    // 4 independent 256-bit loads (the proven MLP depth)
    float v0[8], v1[8], v2[8], v3[8];
    ldg256_nc(srow,                          v0);
    ldg256_nc(srow + DIM,                    v1);
    ldg256_nc(srow + (size_t)W2 * DIM,       v2);
    ldg256_nc(srow + (size_t)(W2 + 1) * DIM, v3);

    float s[8];
#pragma unroll
    for (int i = 0; i < 8; i++)
        s[i] = (v0[i] + v1[i] + v2[i] + v3[i]) * 0.25f;

    stg256_cs(o, s);

    if (t == 0 && out_att) out_att[(size_t)b * MAXT + j] = 1.f;
}

extern "C" void kernel_launch(void* const* d_in, const int* in_sizes, int n_in,
                              void* d_out, int out_size)
{
    const float* hs       = (const float*)d_in[0];  // [B, S, D] float32
    // d_in[1] = attention_mask (values unused by reference math)
    const int*   grid_thw = (const int*)d_in[2];    // [B, 3] int32

    float* out = (float*)d_out;
    const long long main_elems = (long long)BATCH * MAXT * DIM;
    const long long att_elems  = (long long)BATCH * MAXT;
    float* out_att = ((long long)out_size >= main_elems + att_elems)
                         ? out + main_elems : nullptr;

    dim3 grid(MAXT, BATCH);
    avg_pool_merge_v8s_kernel<<<grid, THREADS>>>(hs, grid_thw, out, out_att);
}